// round 1
// baseline (speedup 1.0000x reference)
#include <cuda_runtime.h>
#include <math.h>

// ---------------------------------------------------------------------------
// Problem: B=8, S=2048, D=1024, fp32
//   scores = causal(x @ x^T / sqrt(D));  P = softmax(scores)
//   attn   = P @ x
//   y      = attn @ W^T
// Scratch lives in __device__ globals (no allocation allowed).
// ---------------------------------------------------------------------------

#define BATCH 8
#define SEQ   2048
#define DIM   1024

#define BM 128
#define BN 128
#define BK 16
// 256 threads, each computes an 8x8 tile of C.

static __device__ float g_scores[BATCH * SEQ * SEQ];  // 134 MB
static __device__ float g_attn[BATCH * SEQ * DIM];    //  67 MB

// ---------------------------------------------------------------------------
// C[m,n] = scale * sum_k A[m,k] * B[n,k]      (both operands K-contiguous, NT)
// Optional causal tile skip (square tiles: skip when n-tile above m-tile).
// ---------------------------------------------------------------------------
__global__ __launch_bounds__(256) void gemm_nt_kernel(
    const float* __restrict__ A, const float* __restrict__ B, float* __restrict__ C,
    int M, int N, int K, float scale,
    long strideA, long strideB, long strideC, int causal)
{
    A += (long)blockIdx.z * strideA;
    B += (long)blockIdx.z * strideB;
    C += (long)blockIdx.z * strideC;

    const int m0 = blockIdx.y * BM;
    const int n0 = blockIdx.x * BN;
    if (causal && n0 > m0 + BM - 1) return;   // fully-masked tile

    __shared__ float As[BK][BM];
    __shared__ float Bs[BK][BN];

    const int tid = threadIdx.x;
    const int ty  = tid / 16;   // 0..15 (m direction)
    const int tx  = tid % 16;   // 0..15 (n direction)

    float acc[8][8];
#pragma unroll
    for (int i = 0; i < 8; i++)
#pragma unroll
        for (int j = 0; j < 8; j++) acc[i][j] = 0.f;

    for (int k0 = 0; k0 < K; k0 += BK) {
        // Load A tile [BM x BK] and B tile [BN x BK], transposed into smem.
#pragma unroll
        for (int it = 0; it < 2; it++) {
            int idx  = tid + it * 256;       // 0..511 (float4 id)
            int row  = idx >> 2;             // 0..127
            int col4 = (idx & 3) << 2;       // 0,4,8,12
            float4 va = *(const float4*)&A[(long)(m0 + row) * K + k0 + col4];
            As[col4 + 0][row] = va.x;
            As[col4 + 1][row] = va.y;
            As[col4 + 2][row] = va.z;
            As[col4 + 3][row] = va.w;
            float4 vb = *(const float4*)&B[(long)(n0 + row) * K + k0 + col4];
            Bs[col4 + 0][row] = vb.x;
            Bs[col4 + 1][row] = vb.y;
            Bs[col4 + 2][row] = vb.z;
            Bs[col4 + 3][row] = vb.w;
        }
        __syncthreads();

#pragma unroll
        for (int kk = 0; kk < BK; kk++) {
            float4 a0 = *(const float4*)&As[kk][ty * 8];
            float4 a1 = *(const float4*)&As[kk][ty * 8 + 4];
            float4 b0 = *(const float4*)&Bs[kk][tx * 8];
            float4 b1 = *(const float4*)&Bs[kk][tx * 8 + 4];
            float a[8] = {a0.x, a0.y, a0.z, a0.w, a1.x, a1.y, a1.z, a1.w};
            float b[8] = {b0.x, b0.y, b0.z, b0.w, b1.x, b1.y, b1.z, b1.w};
#pragma unroll
            for (int i = 0; i < 8; i++)
#pragma unroll
                for (int j = 0; j < 8; j++) acc[i][j] += a[i] * b[j];
        }
        __syncthreads();
    }

#pragma unroll
    for (int i = 0; i < 8; i++) {
        int m = m0 + ty * 8 + i;
#pragma unroll
        for (int j = 0; j < 8; j += 4) {
            float4 v;
            v.x = acc[i][j + 0] * scale;
            v.y = acc[i][j + 1] * scale;
            v.z = acc[i][j + 2] * scale;
            v.w = acc[i][j + 3] * scale;
            *(float4*)&C[(long)m * N + n0 + tx * 8 + j] = v;
        }
    }
}

// ---------------------------------------------------------------------------
// C[m,n] = sum_k A[m,k] * B[k,n]   (NN). Optional causal k-limit:
// rows in this m-tile only attend to k < m0+BM, so clip the K loop.
// ---------------------------------------------------------------------------
__global__ __launch_bounds__(256) void gemm_nn_kernel(
    const float* __restrict__ A, const float* __restrict__ B, float* __restrict__ C,
    int M, int N, int K,
    long strideA, long strideB, long strideC, int klimit)
{
    A += (long)blockIdx.z * strideA;
    B += (long)blockIdx.z * strideB;
    C += (long)blockIdx.z * strideC;

    const int m0 = blockIdx.y * BM;
    const int n0 = blockIdx.x * BN;
    const int kmax = klimit ? min(K, m0 + BM) : K;

    __shared__ float As[BK][BM];
    __shared__ float Bs[BK][BN];

    const int tid = threadIdx.x;
    const int ty  = tid / 16;
    const int tx  = tid % 16;

    float acc[8][8];
#pragma unroll
    for (int i = 0; i < 8; i++)
#pragma unroll
        for (int j = 0; j < 8; j++) acc[i][j] = 0.f;

    for (int k0 = 0; k0 < kmax; k0 += BK) {
#pragma unroll
        for (int it = 0; it < 2; it++) {
            int idx  = tid + it * 256;       // 0..511
            // A tile [BM rows x BK cols], K-contiguous -> transpose into As
            int arow  = idx >> 2;
            int acol4 = (idx & 3) << 2;
            float4 va = *(const float4*)&A[(long)(m0 + arow) * K + k0 + acol4];
            As[acol4 + 0][arow] = va.x;
            As[acol4 + 1][arow] = va.y;
            As[acol4 + 2][arow] = va.z;
            As[acol4 + 3][arow] = va.w;
            // B tile [BK rows x BN cols], N-contiguous -> direct store
            int brow  = idx >> 5;            // 0..15
            int bcol4 = (idx & 31) << 2;     // 0..124
            float4 vb = *(const float4*)&B[(long)(k0 + brow) * N + n0 + bcol4];
            *(float4*)&Bs[brow][bcol4] = vb;
        }
        __syncthreads();

#pragma unroll
        for (int kk = 0; kk < BK; kk++) {
            float4 a0 = *(const float4*)&As[kk][ty * 8];
            float4 a1 = *(const float4*)&As[kk][ty * 8 + 4];
            float4 b0 = *(const float4*)&Bs[kk][tx * 8];
            float4 b1 = *(const float4*)&Bs[kk][tx * 8 + 4];
            float a[8] = {a0.x, a0.y, a0.z, a0.w, a1.x, a1.y, a1.z, a1.w};
            float b[8] = {b0.x, b0.y, b0.z, b0.w, b1.x, b1.y, b1.z, b1.w};
#pragma unroll
            for (int i = 0; i < 8; i++)
#pragma unroll
                for (int j = 0; j < 8; j++) acc[i][j] += a[i] * b[j];
        }
        __syncthreads();
    }

#pragma unroll
    for (int i = 0; i < 8; i++) {
        int m = m0 + ty * 8 + i;
#pragma unroll
        for (int j = 0; j < 8; j += 4) {
            float4 v;
            v.x = acc[i][j + 0];
            v.y = acc[i][j + 1];
            v.z = acc[i][j + 2];
            v.w = acc[i][j + 3];
            *(float4*)&C[(long)m * N + n0 + tx * 8 + j] = v;
        }
    }
}

// ---------------------------------------------------------------------------
// Causal row softmax over scores[B,S,S] in place.
// One block (256 threads) per row; row cached in registers (2048/256 = 8).
// Entries k > q are set to 0 so the following dense GEMM is correct.
// ---------------------------------------------------------------------------
__global__ __launch_bounds__(256) void softmax_kernel(float* __restrict__ scores)
{
    const long row = blockIdx.x;            // 0 .. B*S-1
    const int  q   = (int)(row % SEQ);
    float* p = scores + row * (long)SEQ;
    const int tid = threadIdx.x;
    const int len = q + 1;

    __shared__ float red[8];

    float v[8];
    float m = -1e30f;
#pragma unroll
    for (int j = 0; j < 8; j++) {
        int i = tid + j * 256;
        v[j] = (i < len) ? p[i] : -1e30f;
        m = fmaxf(m, v[j]);
    }
#pragma unroll
    for (int o = 16; o > 0; o >>= 1) m = fmaxf(m, __shfl_xor_sync(0xffffffffu, m, o));
    if ((tid & 31) == 0) red[tid >> 5] = m;
    __syncthreads();
    float m_all = red[0];
#pragma unroll
    for (int w = 1; w < 8; w++) m_all = fmaxf(m_all, red[w]);
    __syncthreads();

    float s = 0.f;
#pragma unroll
    for (int j = 0; j < 8; j++) {
        v[j] = __expf(v[j] - m_all);
        s += v[j];
    }
#pragma unroll
    for (int o = 16; o > 0; o >>= 1) s += __shfl_xor_sync(0xffffffffu, s, o);
    if ((tid & 31) == 0) red[tid >> 5] = s;
    __syncthreads();
    float s_all = 0.f;
#pragma unroll
    for (int w = 0; w < 8; w++) s_all += red[w];
    const float inv = 1.f / s_all;

#pragma unroll
    for (int j = 0; j < 8; j++) {
        int i = tid + j * 256;
        p[i] = (i < len) ? v[j] * inv : 0.f;
    }
}

// ---------------------------------------------------------------------------

extern "C" void kernel_launch(void* const* d_in, const int* in_sizes, int n_in,
                              void* d_out, int out_size)
{
    const float* x = (const float*)d_in[0];   // [B, S, D]
    const float* W = (const float*)d_in[1];   // [D, D]
    float* out = (float*)d_out;               // [B, S, D]

    float* scores = nullptr;
    float* attn   = nullptr;
    cudaGetSymbolAddress((void**)&scores, g_scores);
    cudaGetSymbolAddress((void**)&attn,   g_attn);

    const float scale = 1.0f / sqrtf((float)DIM);   // 0.03125
    dim3 blk(256);

    // 1) scores = scale * x @ x^T  (causal tiles only)
    gemm_nt_kernel<<<dim3(SEQ / BN, SEQ / BM, BATCH), blk>>>(
        x, x, scores, SEQ, SEQ, DIM, scale,
        (long)SEQ * DIM, (long)SEQ * DIM, (long)SEQ * SEQ, 1);

    // 2) causal softmax in place (zeros masked region)
    softmax_kernel<<<BATCH * SEQ, 256>>>(scores);

    // 3) attn = P @ x  (k-limited per row tile)
    gemm_nn_kernel<<<dim3(DIM / BN, SEQ / BM, BATCH), blk>>>(
        scores, x, attn, SEQ, DIM, SEQ,
        (long)SEQ * SEQ, (long)SEQ * DIM, (long)SEQ * DIM, 1);

    // 4) y = attn @ W^T   (flatten batch: M = B*S)
    gemm_nt_kernel<<<dim3(DIM / BN, (BATCH * SEQ) / BM, 1), blk>>>(
        attn, W, out, BATCH * SEQ, DIM, DIM, 1.0f,
        0, 0, 0, 0);
}

// round 2
// speedup vs baseline: 1.4842x; 1.4842x over previous
#include <cuda_runtime.h>
#include <mma.h>
#include <math.h>

using namespace nvcuda;

// ---------------------------------------------------------------------------
// Problem: B=8, S=2048, D=1024, fp32
//   scores = causal(x @ x^T / sqrt(D));  P = softmax(scores)
//   attn   = P @ x
//   y      = attn @ W^T
// GEMMs on tensor pipe via TF32 wmma (m16n16k8).
// ---------------------------------------------------------------------------

#define BATCH 8
#define SEQ   2048
#define DIM   1024

#define BM 128
#define BN 128
#define BK 16
#define BKP 20    // padded k-stride for row-major smem tiles (bank spread)
#define BNP 132   // padded n-stride for the NN B tile

// 8 warps (256 thr): warp grid 2 (m) x 4 (n); each warp owns 64x32 = 4x2 wmma tiles.

static __device__ float g_scores[BATCH * SEQ * SEQ];  // 134 MB
static __device__ float g_attn[BATCH * SEQ * DIM];    //  67 MB

using FragA  = wmma::fragment<wmma::matrix_a, 16, 16, 8, wmma::precision::tf32, wmma::row_major>;
using FragBc = wmma::fragment<wmma::matrix_b, 16, 16, 8, wmma::precision::tf32, wmma::col_major>;
using FragBr = wmma::fragment<wmma::matrix_b, 16, 16, 8, wmma::precision::tf32, wmma::row_major>;
using FragC  = wmma::fragment<wmma::accumulator, 16, 16, 8, float>;

template <class F>
__device__ __forceinline__ void to_tf32(F& f) {
#pragma unroll
    for (int i = 0; i < f.num_elements; i++) f.x[i] = wmma::__float_to_tf32(f.x[i]);
}

// ---------------------------------------------------------------------------
// NT: C[m,n] = scale * sum_k A[m,k] * B[n,k]   (both K-contiguous)
// ---------------------------------------------------------------------------
__global__ __launch_bounds__(256) void gemm_nt_tc(
    const float* __restrict__ A, const float* __restrict__ B, float* __restrict__ C,
    int M, int N, int K, float scale,
    long strideA, long strideB, long strideC, int causal)
{
    A += (long)blockIdx.z * strideA;
    B += (long)blockIdx.z * strideB;
    C += (long)blockIdx.z * strideC;

    const int m0 = blockIdx.y * BM;
    const int n0 = blockIdx.x * BN;
    if (causal && n0 > m0 + BM - 1) return;

    __shared__ float As[BM][BKP];
    __shared__ float Bs[BN][BKP];

    const int tid    = threadIdx.x;
    const int warpId = tid >> 5;
    const int wm     = warpId & 1;   // 0..1 -> 64-row slab
    const int wn     = warpId >> 1;  // 0..3 -> 32-col slab

    FragC acc[4][2];
#pragma unroll
    for (int i = 0; i < 4; i++)
#pragma unroll
        for (int j = 0; j < 2; j++) wmma::fill_fragment(acc[i][j], 0.f);

    for (int k0 = 0; k0 < K; k0 += BK) {
#pragma unroll
        for (int it = 0; it < 2; it++) {
            int idx  = tid + it * 256;      // 0..511
            int row  = idx >> 2;
            int col4 = (idx & 3) << 2;
            *(float4*)&As[row][col4] = *(const float4*)&A[(long)(m0 + row) * K + k0 + col4];
            *(float4*)&Bs[row][col4] = *(const float4*)&B[(long)(n0 + row) * K + k0 + col4];
        }
        __syncthreads();

#pragma unroll
        for (int kk = 0; kk < BK; kk += 8) {
            FragA a[4];
            FragBc b[2];
#pragma unroll
            for (int i = 0; i < 4; i++) {
                wmma::load_matrix_sync(a[i], &As[wm * 64 + i * 16][kk], BKP);
                to_tf32(a[i]);
            }
#pragma unroll
            for (int j = 0; j < 2; j++) {
                wmma::load_matrix_sync(b[j], &Bs[wn * 32 + j * 16][kk], BKP);
                to_tf32(b[j]);
            }
#pragma unroll
            for (int i = 0; i < 4; i++)
#pragma unroll
                for (int j = 0; j < 2; j++)
                    wmma::mma_sync(acc[i][j], a[i], b[j], acc[i][j]);
        }
        __syncthreads();
    }

#pragma unroll
    for (int i = 0; i < 4; i++)
#pragma unroll
        for (int j = 0; j < 2; j++) {
#pragma unroll
            for (int e = 0; e < acc[i][j].num_elements; e++) acc[i][j].x[e] *= scale;
            wmma::store_matrix_sync(
                &C[(long)(m0 + wm * 64 + i * 16) * N + n0 + wn * 32 + j * 16],
                acc[i][j], N, wmma::mem_row_major);
        }
}

// ---------------------------------------------------------------------------
// NN: C[m,n] = sum_k A[m,k] * B[k,n]; optional causal k-limit (k < m0+BM)
// ---------------------------------------------------------------------------
__global__ __launch_bounds__(256) void gemm_nn_tc(
    const float* __restrict__ A, const float* __restrict__ B, float* __restrict__ C,
    int M, int N, int K,
    long strideA, long strideB, long strideC, int klimit)
{
    A += (long)blockIdx.z * strideA;
    B += (long)blockIdx.z * strideB;
    C += (long)blockIdx.z * strideC;

    const int m0 = blockIdx.y * BM;
    const int n0 = blockIdx.x * BN;
    const int kmax = klimit ? min(K, m0 + BM) : K;

    __shared__ float As[BM][BKP];
    __shared__ float Bs[BK][BNP];

    const int tid    = threadIdx.x;
    const int warpId = tid >> 5;
    const int wm     = warpId & 1;
    const int wn     = warpId >> 1;

    FragC acc[4][2];
#pragma unroll
    for (int i = 0; i < 4; i++)
#pragma unroll
        for (int j = 0; j < 2; j++) wmma::fill_fragment(acc[i][j], 0.f);

    for (int k0 = 0; k0 < kmax; k0 += BK) {
#pragma unroll
        for (int it = 0; it < 2; it++) {
            int idx  = tid + it * 256;      // 0..511
            int arow  = idx >> 2;
            int acol4 = (idx & 3) << 2;
            *(float4*)&As[arow][acol4] = *(const float4*)&A[(long)(m0 + arow) * K + k0 + acol4];
            int brow  = idx >> 5;           // 0..15
            int bcol4 = (idx & 31) << 2;    // 0..124
            *(float4*)&Bs[brow][bcol4] = *(const float4*)&B[(long)(k0 + brow) * N + n0 + bcol4];
        }
        __syncthreads();

#pragma unroll
        for (int kk = 0; kk < BK; kk += 8) {
            FragA a[4];
            FragBr b[2];
#pragma unroll
            for (int i = 0; i < 4; i++) {
                wmma::load_matrix_sync(a[i], &As[wm * 64 + i * 16][kk], BKP);
                to_tf32(a[i]);
            }
#pragma unroll
            for (int j = 0; j < 2; j++) {
                wmma::load_matrix_sync(b[j], &Bs[kk][wn * 32 + j * 16], BNP);
                to_tf32(b[j]);
            }
#pragma unroll
            for (int i = 0; i < 4; i++)
#pragma unroll
                for (int j = 0; j < 2; j++)
                    wmma::mma_sync(acc[i][j], a[i], b[j], acc[i][j]);
        }
        __syncthreads();
    }

#pragma unroll
    for (int i = 0; i < 4; i++)
#pragma unroll
        for (int j = 0; j < 2; j++)
            wmma::store_matrix_sync(
                &C[(long)(m0 + wm * 64 + i * 16) * N + n0 + wn * 32 + j * 16],
                acc[i][j], N, wmma::mem_row_major);
}

// ---------------------------------------------------------------------------
// Causal row softmax over scores[B,S,S] in place; masked entries -> 0.
// ---------------------------------------------------------------------------
__global__ __launch_bounds__(256) void softmax_kernel(float* __restrict__ scores)
{
    const long row = blockIdx.x;
    const int  q   = (int)(row % SEQ);
    float* p = scores + row * (long)SEQ;
    const int tid = threadIdx.x;
    const int len = q + 1;

    __shared__ float red[8];

    float v[8];
    float m = -1e30f;
#pragma unroll
    for (int j = 0; j < 8; j++) {
        int i = tid + j * 256;
        v[j] = (i < len) ? p[i] : -1e30f;
        m = fmaxf(m, v[j]);
    }
#pragma unroll
    for (int o = 16; o > 0; o >>= 1) m = fmaxf(m, __shfl_xor_sync(0xffffffffu, m, o));
    if ((tid & 31) == 0) red[tid >> 5] = m;
    __syncthreads();
    float m_all = red[0];
#pragma unroll
    for (int w = 1; w < 8; w++) m_all = fmaxf(m_all, red[w]);
    __syncthreads();

    float s = 0.f;
#pragma unroll
    for (int j = 0; j < 8; j++) {
        v[j] = __expf(v[j] - m_all);
        s += v[j];
    }
#pragma unroll
    for (int o = 16; o > 0; o >>= 1) s += __shfl_xor_sync(0xffffffffu, s, o);
    if ((tid & 31) == 0) red[tid >> 5] = s;
    __syncthreads();
    float s_all = 0.f;
#pragma unroll
    for (int w = 0; w < 8; w++) s_all += red[w];
    const float inv = 1.f / s_all;

#pragma unroll
    for (int j = 0; j < 8; j++) {
        int i = tid + j * 256;
        p[i] = (i < len) ? v[j] * inv : 0.f;
    }
}

// ---------------------------------------------------------------------------

extern "C" void kernel_launch(void* const* d_in, const int* in_sizes, int n_in,
                              void* d_out, int out_size)
{
    const float* x = (const float*)d_in[0];   // [B, S, D]
    const float* W = (const float*)d_in[1];   // [D, D]
    float* out = (float*)d_out;               // [B, S, D]

    float* scores = nullptr;
    float* attn   = nullptr;
    cudaGetSymbolAddress((void**)&scores, g_scores);
    cudaGetSymbolAddress((void**)&attn,   g_attn);

    const float scale = 1.0f / sqrtf((float)DIM);
    dim3 blk(256);

    // 1) scores = scale * x @ x^T  (causal tiles only)
    gemm_nt_tc<<<dim3(SEQ / BN, SEQ / BM, BATCH), blk>>>(
        x, x, scores, SEQ, SEQ, DIM, scale,
        (long)SEQ * DIM, (long)SEQ * DIM, (long)SEQ * SEQ, 1);

    // 2) causal softmax in place (zeros masked region)
    softmax_kernel<<<BATCH * SEQ, 256>>>(scores);

    // 3) attn = P @ x  (k-limited per row tile)
    gemm_nn_tc<<<dim3(DIM / BN, SEQ / BM, BATCH), blk>>>(
        scores, x, attn, SEQ, DIM, SEQ,
        (long)SEQ * SEQ, (long)SEQ * DIM, (long)SEQ * DIM, 1);

    // 4) y = attn @ W^T   (flatten batch: M = B*S)
    gemm_nt_tc<<<dim3(DIM / BN, (BATCH * SEQ) / BM, 1), blk>>>(
        attn, W, out, BATCH * SEQ, DIM, DIM, 1.0f,
        0, 0, 0, 0);
}

// round 5
// speedup vs baseline: 3.2511x; 2.1904x over previous
#include <cuda_runtime.h>
#include <cstdint>
#include <math.h>

// ===========================================================================
// B=8, S=2048, D=1024 fp32.
//   scores = causal(x x^T / 32); P = softmax(scores); attn = P x; y = attn W^T
// GEMM engine: mma.sync.m16n8k8 TF32 (sm_103 baseline ISA; tcgen05 is not
// available through this harness's compute_103 virtual arch).
// 128x128 CTA tile, BK=32, 3-stage cp.async pipeline, conflict-free smem.
// ===========================================================================

#define BATCH 8
#define SEQ   2048
#define DIM   1024

#define TM 128
#define TN 128
#define CK 32                 // K floats per pipeline chunk
#define LDK 36                // smem row stride in floats (32 + 4 pad -> conflict-free)
#define NSTAGE 3
#define A_FLOATS (TM * LDK)               // 4608
#define STAGE_FLOATS (2 * A_FLOATS)       // A tile + B tile
#define DSMEM_SZ (NSTAGE * STAGE_FLOATS * 4)   // 110592 B

static __device__ float g_scores[(long)BATCH * SEQ * SEQ];  // 134 MB (P in place)
static __device__ float g_xr[(long)BATCH * SEQ * DIM];      // tf32-rounded x
static __device__ float g_xT[(long)BATCH * DIM * SEQ];      // tf32-rounded x^T
static __device__ float g_attn[(long)BATCH * SEQ * DIM];
static __device__ float g_Wr[DIM * DIM];                    // tf32-rounded W

// ---------------------------------------------------------------- helpers --
__device__ __forceinline__ uint32_t smem_u32(const void* p) {
    uint32_t a;
    asm("{ .reg .u64 t; cvta.to.shared.u64 t, %1; cvt.u32.u64 %0, t; }"
        : "=r"(a) : "l"(p));
    return a;
}
__device__ __forceinline__ float tf32r(float x) {
    float y; asm("cvt.rna.tf32.f32 %0, %1;" : "=f"(y) : "f"(x)); return y;
}
__device__ __forceinline__ void cp_async16(uint32_t s, const void* g) {
    asm volatile("cp.async.cg.shared.global [%0], [%1], 16;" :: "r"(s), "l"(g));
}
#define CP_COMMIT() asm volatile("cp.async.commit_group;" ::: "memory")
#define CP_WAIT(n)  asm volatile("cp.async.wait_group %0;" :: "n"(n) : "memory")

__device__ __forceinline__ void mma_tf32(float c[4], const uint32_t a[4], const uint32_t b[2]) {
    asm volatile(
        "mma.sync.aligned.m16n8k8.row.col.f32.tf32.tf32.f32 "
        "{%0,%1,%2,%3}, {%4,%5,%6,%7}, {%8,%9}, {%0,%1,%2,%3};"
        : "+f"(c[0]), "+f"(c[1]), "+f"(c[2]), "+f"(c[3])
        : "r"(a[0]), "r"(a[1]), "r"(a[2]), "r"(a[3]), "r"(b[0]), "r"(b[1]));
}

// ---------------------------------------------------------------- GEMM NT --
// C[m,n] = scale * sum_k A[m,k] * B[n,k]   (both K-contiguous fp32, tf32 mma)
__global__ __launch_bounds__(256) void gemm_nt_mma(
    const float* __restrict__ A, const float* __restrict__ B, float* __restrict__ C,
    int K, int lda, int ldb, int ldc,
    long sA, long sB, long sC,
    float scale, int causal, int klimit, int roundOut)
{
    extern __shared__ float smem[];

    A += (long)blockIdx.z * sA;
    B += (long)blockIdx.z * sB;
    C += (long)blockIdx.z * sC;

    const int m0 = blockIdx.y * TM;
    const int n0 = blockIdx.x * TN;
    if (causal && n0 > m0 + TM - 1) return;
    const int kmax = klimit ? min(K, m0 + TM) : K;
    const int nch  = kmax / CK;

    const int tid   = threadIdx.x;
    const int lane  = tid & 31;
    const int wid   = tid >> 5;
    const int warpM = wid & 1;      // 0..1 -> 64-row slab
    const int warpN = wid >> 1;     // 0..3 -> 32-col slab
    const int qr    = lane >> 2;    // 0..7
    const int qk    = lane & 3;     // 0..3

    const uint32_t sbase = smem_u32(smem);

    // gmem load mapping: 8 float4 per 32-float row; 256 threads -> 4 iters/tile
    const int grow = tid >> 3;          // 0..31 step base (with +32*i)
    const int gk4  = (tid & 7) << 2;    // 0,4,...,28

    float acc[16][4];
#pragma unroll
    for (int i = 0; i < 16; i++)
#pragma unroll
        for (int j = 0; j < 4; j++) acc[i][j] = 0.f;

    // ---- stage loader (chunk c into slot s) ----
    auto load_stage = [&](int s, int c) {
        const uint32_t st = sbase + (uint32_t)(s * STAGE_FLOATS) * 4u;
        const float* gA = A + (long)m0 * lda + c * CK;
        const float* gB = B + (long)n0 * ldb + c * CK;
#pragma unroll
        for (int i = 0; i < 4; i++) {
            int row = grow + i * 32;
            cp_async16(st + (uint32_t)(row * LDK + gk4) * 4u,
                       gA + (long)row * lda + gk4);
        }
#pragma unroll
        for (int i = 0; i < 4; i++) {
            int row = grow + i * 32;
            cp_async16(st + (uint32_t)(A_FLOATS + row * LDK + gk4) * 4u,
                       gB + (long)row * ldb + gk4);
        }
    };

    // ---- prologue ----
#pragma unroll
    for (int s = 0; s < NSTAGE - 1; s++) {
        if (s < nch) load_stage(s, s);
        CP_COMMIT();
    }

    // ---- main loop ----
    for (int c = 0; c < nch; c++) {
        CP_WAIT(NSTAGE - 2);
        __syncthreads();

        const int pf = c + NSTAGE - 1;
        if (pf < nch) load_stage(pf % NSTAGE, pf);
        CP_COMMIT();

        const float* sA = smem + (c % NSTAGE) * STAGE_FLOATS;
        const float* sB = sA + A_FLOATS;
        const float* pa0 = sA + (warpM * 64 + qr) * LDK + qk;
        const float* pb0 = sB + (warpN * 32 + qr) * LDK + qk;

#pragma unroll
        for (int kk = 0; kk < CK; kk += 8) {
            uint32_t a[4][4], b[4][2];
#pragma unroll
            for (int mf = 0; mf < 4; mf++) {
                const float* p = pa0 + mf * 16 * LDK + kk;
                a[mf][0] = __float_as_uint(p[0]);
                a[mf][1] = __float_as_uint(p[8 * LDK]);
                a[mf][2] = __float_as_uint(p[4]);
                a[mf][3] = __float_as_uint(p[8 * LDK + 4]);
            }
#pragma unroll
            for (int nf = 0; nf < 4; nf++) {
                const float* p = pb0 + nf * 8 * LDK + kk;
                b[nf][0] = __float_as_uint(p[0]);
                b[nf][1] = __float_as_uint(p[4]);
            }
#pragma unroll
            for (int mf = 0; mf < 4; mf++)
#pragma unroll
                for (int nf = 0; nf < 4; nf++)
                    mma_tf32(acc[mf * 4 + nf], a[mf], b[nf]);
        }
    }

    // ---- epilogue ----
#pragma unroll
    for (int mf = 0; mf < 4; mf++) {
        const int m = m0 + warpM * 64 + mf * 16 + qr;
#pragma unroll
        for (int nf = 0; nf < 4; nf++) {
            const int n = n0 + warpN * 32 + nf * 8 + 2 * qk;
            float* c0 = acc[mf * 4 + nf];
            float v0 = c0[0] * scale, v1 = c0[1] * scale;
            float v2 = c0[2] * scale, v3 = c0[3] * scale;
            if (roundOut) { v0 = tf32r(v0); v1 = tf32r(v1); v2 = tf32r(v2); v3 = tf32r(v3); }
            *(float2*)&C[(long)m * ldc + n]       = make_float2(v0, v1);
            *(float2*)&C[(long)(m + 8) * ldc + n] = make_float2(v2, v3);
        }
    }
}

// ---------------------------------------------------------------- elementwise
__global__ __launch_bounds__(256) void round_kernel(const float* __restrict__ in,
                                                    float* __restrict__ out, long n4)
{
    long i = (long)blockIdx.x * blockDim.x + threadIdx.x;
    if (i >= n4) return;
    float4 v = ((const float4*)in)[i];
    v.x = tf32r(v.x); v.y = tf32r(v.y); v.z = tf32r(v.z); v.w = tf32r(v.w);
    ((float4*)out)[i] = v;
}

// x[b][s][d] fp32 -> xT[b][d][s] tf32-rounded
__global__ __launch_bounds__(256) void transpose_round(const float* __restrict__ x,
                                                       float* __restrict__ xT)
{
    __shared__ float t[32][33];
    const int b  = blockIdx.z;
    const int s0 = blockIdx.x * 32;
    const int d0 = blockIdx.y * 32;
    const float* xb = x + (long)b * SEQ * DIM;
    float* ob = xT + (long)b * DIM * SEQ;
    const int tx = threadIdx.x & 31;
    const int tg = threadIdx.x >> 5;
#pragma unroll
    for (int r = 0; r < 4; r++) {
        int row = tg * 4 + r;
        t[row][tx] = xb[(long)(s0 + row) * DIM + d0 + tx];
    }
    __syncthreads();
#pragma unroll
    for (int r = 0; r < 4; r++) {
        int row = tg * 4 + r;
        ob[(long)(d0 + row) * SEQ + s0 + tx] = tf32r(t[tx][row]);
    }
}

// ---------------------------------------------------------------- softmax --
// in-place causal softmax; output tf32-rounded, masked entries -> 0
__global__ __launch_bounds__(256) void softmax_kernel(float* __restrict__ scores)
{
    const long row = blockIdx.x;
    const int  q   = (int)(row % SEQ);
    float* p = scores + row * (long)SEQ;
    const int tid = threadIdx.x;
    const int len = q + 1;

    __shared__ float red[8];

    float v[8];
    float m = -1e30f;
#pragma unroll
    for (int j = 0; j < 8; j++) {
        int i = tid + j * 256;
        v[j] = (i < len) ? p[i] : -1e30f;
        m = fmaxf(m, v[j]);
    }
#pragma unroll
    for (int o = 16; o > 0; o >>= 1) m = fmaxf(m, __shfl_xor_sync(0xffffffffu, m, o));
    if ((tid & 31) == 0) red[tid >> 5] = m;
    __syncthreads();
    float m_all = red[0];
#pragma unroll
    for (int w = 1; w < 8; w++) m_all = fmaxf(m_all, red[w]);
    __syncthreads();

    float s = 0.f;
#pragma unroll
    for (int j = 0; j < 8; j++) {
        v[j] = __expf(v[j] - m_all);
        s += v[j];
    }
#pragma unroll
    for (int o = 16; o > 0; o >>= 1) s += __shfl_xor_sync(0xffffffffu, s, o);
    if ((tid & 31) == 0) red[tid >> 5] = s;
    __syncthreads();
    float s_all = 0.f;
#pragma unroll
    for (int w = 0; w < 8; w++) s_all += red[w];
    const float inv = 1.f / s_all;

#pragma unroll
    for (int j = 0; j < 8; j++) {
        int i = tid + j * 256;
        p[i] = (i < len) ? tf32r(v[j] * inv) : 0.f;
    }
}

// ---------------------------------------------------------------------------
extern "C" void kernel_launch(void* const* d_in, const int* in_sizes, int n_in,
                              void* d_out, int out_size)
{
    const float* x = (const float*)d_in[0];   // [B,S,D]
    const float* W = (const float*)d_in[1];   // [D,D]
    float* out = (float*)d_out;

    float *scores, *xr, *xT, *attn, *Wr;
    cudaGetSymbolAddress((void**)&scores, g_scores);
    cudaGetSymbolAddress((void**)&xr, g_xr);
    cudaGetSymbolAddress((void**)&xT, g_xT);
    cudaGetSymbolAddress((void**)&attn, g_attn);
    cudaGetSymbolAddress((void**)&Wr, g_Wr);

    cudaFuncSetAttribute(gemm_nt_mma,
                         cudaFuncAttributeMaxDynamicSharedMemorySize, DSMEM_SZ);

    const float scale = 1.0f / 32.0f;   // 1/sqrt(1024)
    dim3 blk(256);

    // tf32-round x / W; build rounded x^T
    round_kernel<<<((long)BATCH * SEQ * DIM / 4 + 255) / 256, blk>>>(
        x, xr, (long)BATCH * SEQ * DIM / 4);
    round_kernel<<<(DIM * DIM / 4 + 255) / 256, blk>>>(W, Wr, (long)DIM * DIM / 4);
    transpose_round<<<dim3(SEQ / 32, DIM / 32, BATCH), blk>>>(x, xT);

    // 1) scores = scale * x x^T  (causal tiles only)
    gemm_nt_mma<<<dim3(SEQ / TN, SEQ / TM, BATCH), blk, DSMEM_SZ>>>(
        xr, xr, scores, DIM, DIM, DIM, SEQ,
        (long)SEQ * DIM, (long)SEQ * DIM, (long)SEQ * SEQ,
        scale, 1, 0, 0);

    // 2) causal softmax in place (rounds P to tf32)
    softmax_kernel<<<BATCH * SEQ, blk>>>(scores);

    // 3) attn = P x  (B = x^T, k-limited), output tf32-rounded
    gemm_nt_mma<<<dim3(DIM / TN, SEQ / TM, BATCH), blk, DSMEM_SZ>>>(
        scores, xT, attn, SEQ, SEQ, SEQ, DIM,
        (long)SEQ * SEQ, (long)DIM * SEQ, (long)SEQ * DIM,
        1.0f, 0, 1, 1);

    // 4) y = attn W^T  (M = B*S flattened)
    gemm_nt_mma<<<dim3(DIM / TN, (BATCH * SEQ) / TM, 1), blk, DSMEM_SZ>>>(
        attn, Wr, out, DIM, DIM, DIM, DIM,
        0, 0, 0,
        1.0f, 0, 0, 0);
}

// round 6
// speedup vs baseline: 3.5739x; 1.0993x over previous
#include <cuda_runtime.h>
#include <cstdint>
#include <math.h>

// ===========================================================================
// B=8, S=2048, D=1024 fp32.
//   scores = causal(x x^T / 32); P = softmax(scores); attn = P x; y = attn W^T
// GEMM engine: mma.sync.m16n8k8 TF32, 128x128 CTA tile, BK=32, 3-stage
// cp.async pipeline, conflict-free smem, 2 CTAs/SM (reg-capped at 128).
// ===========================================================================

#define BATCH 8
#define SEQ   2048
#define DIM   1024

#define TM 128
#define TN 128
#define CK 32                 // K floats per pipeline chunk
#define LDK 36                // smem row stride in floats (conflict-free)
#define NSTAGE 3
#define A_FLOATS (TM * LDK)               // 4608
#define STAGE_FLOATS (2 * A_FLOATS)
#define DSMEM_SZ (NSTAGE * STAGE_FLOATS * 4)   // 110592 B (x2 CTAs = 221KB <= 228KB)

static __device__ float g_scores[(long)BATCH * SEQ * SEQ];
static __device__ float g_xr[(long)BATCH * SEQ * DIM];
static __device__ float g_xT[(long)BATCH * DIM * SEQ];
static __device__ float g_attn[(long)BATCH * SEQ * DIM];
static __device__ float g_Wr[DIM * DIM];

// ---------------------------------------------------------------- helpers --
__device__ __forceinline__ uint32_t smem_u32(const void* p) {
    uint32_t a;
    asm("{ .reg .u64 t; cvta.to.shared.u64 t, %1; cvt.u32.u64 %0, t; }"
        : "=r"(a) : "l"(p));
    return a;
}
__device__ __forceinline__ float tf32r(float x) {
    float y; asm("cvt.rna.tf32.f32 %0, %1;" : "=f"(y) : "f"(x)); return y;
}
__device__ __forceinline__ void cp_async16(uint32_t s, const void* g) {
    asm volatile("cp.async.cg.shared.global [%0], [%1], 16;" :: "r"(s), "l"(g));
}
#define CP_COMMIT() asm volatile("cp.async.commit_group;" ::: "memory")
#define CP_WAIT(n)  asm volatile("cp.async.wait_group %0;" :: "n"(n) : "memory")

__device__ __forceinline__ void mma_tf32(float c[4], const uint32_t a[4], const uint32_t b[2]) {
    asm volatile(
        "mma.sync.aligned.m16n8k8.row.col.f32.tf32.tf32.f32 "
        "{%0,%1,%2,%3}, {%4,%5,%6,%7}, {%8,%9}, {%0,%1,%2,%3};"
        : "+f"(c[0]), "+f"(c[1]), "+f"(c[2]), "+f"(c[3])
        : "r"(a[0]), "r"(a[1]), "r"(a[2]), "r"(a[3]), "r"(b[0]), "r"(b[1]));
}

// ---------------------------------------------------------------- GEMM NT --
// C[m,n] = scale * sum_k A[m,k] * B[n,k]
__global__ __launch_bounds__(256, 2) void gemm_nt_mma(
    const float* __restrict__ A, const float* __restrict__ B, float* __restrict__ C,
    int K, int lda, int ldb, int ldc,
    long sA, long sB, long sC,
    float scale, int causal, int klimit, int roundOut)
{
    extern __shared__ float smem[];

    A += (long)blockIdx.z * sA;
    B += (long)blockIdx.z * sB;
    C += (long)blockIdx.z * sC;

    const int m0 = blockIdx.y * TM;
    const int n0 = blockIdx.x * TN;
    if (causal && n0 > m0 + TM - 1) return;
    const int kmax = klimit ? min(K, m0 + TM) : K;
    const int nch  = kmax / CK;

    const int tid   = threadIdx.x;
    const int lane  = tid & 31;
    const int wid   = tid >> 5;
    const int warpM = wid & 1;
    const int warpN = wid >> 1;
    const int qr    = lane >> 2;
    const int qk    = lane & 3;

    const uint32_t sbase = smem_u32(smem);

    const int grow = tid >> 3;
    const int gk4  = (tid & 7) << 2;

    float acc[16][4];
#pragma unroll
    for (int i = 0; i < 16; i++)
#pragma unroll
        for (int j = 0; j < 4; j++) acc[i][j] = 0.f;

    auto load_stage = [&](int s, int c) {
        const uint32_t st = sbase + (uint32_t)(s * STAGE_FLOATS) * 4u;
        const float* gA = A + (long)m0 * lda + c * CK;
        const float* gB = B + (long)n0 * ldb + c * CK;
#pragma unroll
        for (int i = 0; i < 4; i++) {
            int row = grow + i * 32;
            cp_async16(st + (uint32_t)(row * LDK + gk4) * 4u,
                       gA + (long)row * lda + gk4);
        }
#pragma unroll
        for (int i = 0; i < 4; i++) {
            int row = grow + i * 32;
            cp_async16(st + (uint32_t)(A_FLOATS + row * LDK + gk4) * 4u,
                       gB + (long)row * ldb + gk4);
        }
    };

#pragma unroll
    for (int s = 0; s < NSTAGE - 1; s++) {
        if (s < nch) load_stage(s, s);
        CP_COMMIT();
    }

    for (int c = 0; c < nch; c++) {
        CP_WAIT(NSTAGE - 2);
        __syncthreads();

        const int pf = c + NSTAGE - 1;
        if (pf < nch) load_stage(pf % NSTAGE, pf);
        CP_COMMIT();

        const float* sA = smem + (c % NSTAGE) * STAGE_FLOATS;
        const float* sB = sA + A_FLOATS;
        const float* pa0 = sA + (warpM * 64 + qr) * LDK + qk;
        const float* pb0 = sB + (warpN * 32 + qr) * LDK + qk;

#pragma unroll
        for (int kk = 0; kk < CK; kk += 8) {
            uint32_t a[4][4], b[4][2];
#pragma unroll
            for (int mf = 0; mf < 4; mf++) {
                const float* p = pa0 + mf * 16 * LDK + kk;
                a[mf][0] = __float_as_uint(p[0]);
                a[mf][1] = __float_as_uint(p[8 * LDK]);
                a[mf][2] = __float_as_uint(p[4]);
                a[mf][3] = __float_as_uint(p[8 * LDK + 4]);
            }
#pragma unroll
            for (int nf = 0; nf < 4; nf++) {
                const float* p = pb0 + nf * 8 * LDK + kk;
                b[nf][0] = __float_as_uint(p[0]);
                b[nf][1] = __float_as_uint(p[4]);
            }
#pragma unroll
            for (int mf = 0; mf < 4; mf++)
#pragma unroll
                for (int nf = 0; nf < 4; nf++)
                    mma_tf32(acc[mf * 4 + nf], a[mf], b[nf]);
        }
    }

#pragma unroll
    for (int mf = 0; mf < 4; mf++) {
        const int m = m0 + warpM * 64 + mf * 16 + qr;
#pragma unroll
        for (int nf = 0; nf < 4; nf++) {
            const int n = n0 + warpN * 32 + nf * 8 + 2 * qk;
            float* c0 = acc[mf * 4 + nf];
            float v0 = c0[0] * scale, v1 = c0[1] * scale;
            float v2 = c0[2] * scale, v3 = c0[3] * scale;
            if (roundOut) { v0 = tf32r(v0); v1 = tf32r(v1); v2 = tf32r(v2); v3 = tf32r(v3); }
            *(float2*)&C[(long)m * ldc + n]       = make_float2(v0, v1);
            *(float2*)&C[(long)(m + 8) * ldc + n] = make_float2(v2, v3);
        }
    }
}

// ---------------------------------------------------------------- elementwise
__global__ __launch_bounds__(256) void round_kernel(const float* __restrict__ in,
                                                    float* __restrict__ out, long n4)
{
    long i = (long)blockIdx.x * blockDim.x + threadIdx.x;
    if (i >= n4) return;
    float4 v = ((const float4*)in)[i];
    v.x = tf32r(v.x); v.y = tf32r(v.y); v.z = tf32r(v.z); v.w = tf32r(v.w);
    ((float4*)out)[i] = v;
}

__global__ __launch_bounds__(256) void transpose_round(const float* __restrict__ x,
                                                       float* __restrict__ xT)
{
    __shared__ float t[32][33];
    const int b  = blockIdx.z;
    const int s0 = blockIdx.x * 32;
    const int d0 = blockIdx.y * 32;
    const float* xb = x + (long)b * SEQ * DIM;
    float* ob = xT + (long)b * DIM * SEQ;
    const int tx = threadIdx.x & 31;
    const int tg = threadIdx.x >> 5;
#pragma unroll
    for (int r = 0; r < 4; r++) {
        int row = tg * 4 + r;
        t[row][tx] = xb[(long)(s0 + row) * DIM + d0 + tx];
    }
    __syncthreads();
#pragma unroll
    for (int r = 0; r < 4; r++) {
        int row = tg * 4 + r;
        ob[(long)(d0 + row) * SEQ + s0 + tx] = tf32r(t[tx][row]);
    }
}

// ---------------------------------------------------------------- softmax --
__global__ __launch_bounds__(256) void softmax_kernel(float* __restrict__ scores)
{
    const long row = blockIdx.x;
    const int  q   = (int)(row % SEQ);
    float* p = scores + row * (long)SEQ;
    const int tid = threadIdx.x;
    const int len = q + 1;

    __shared__ float red[8];

    float v[8];
    float m = -1e30f;
#pragma unroll
    for (int j = 0; j < 8; j++) {
        int i = tid + j * 256;
        v[j] = (i < len) ? p[i] : -1e30f;
        m = fmaxf(m, v[j]);
    }
#pragma unroll
    for (int o = 16; o > 0; o >>= 1) m = fmaxf(m, __shfl_xor_sync(0xffffffffu, m, o));
    if ((tid & 31) == 0) red[tid >> 5] = m;
    __syncthreads();
    float m_all = red[0];
#pragma unroll
    for (int w = 1; w < 8; w++) m_all = fmaxf(m_all, red[w]);
    __syncthreads();

    float s = 0.f;
#pragma unroll
    for (int j = 0; j < 8; j++) {
        v[j] = __expf(v[j] - m_all);
        s += v[j];
    }
#pragma unroll
    for (int o = 16; o > 0; o >>= 1) s += __shfl_xor_sync(0xffffffffu, s, o);
    if ((tid & 31) == 0) red[tid >> 5] = s;
    __syncthreads();
    float s_all = 0.f;
#pragma unroll
    for (int w = 0; w < 8; w++) s_all += red[w];
    const float inv = 1.f / s_all;

#pragma unroll
    for (int j = 0; j < 8; j++) {
        int i = tid + j * 256;
        p[i] = (i < len) ? tf32r(v[j] * inv) : 0.f;
    }
}

// ---------------------------------------------------------------------------
extern "C" void kernel_launch(void* const* d_in, const int* in_sizes, int n_in,
                              void* d_out, int out_size)
{
    const float* x = (const float*)d_in[0];
    const float* W = (const float*)d_in[1];
    float* out = (float*)d_out;

    float *scores, *xr, *xT, *attn, *Wr;
    cudaGetSymbolAddress((void**)&scores, g_scores);
    cudaGetSymbolAddress((void**)&xr, g_xr);
    cudaGetSymbolAddress((void**)&xT, g_xT);
    cudaGetSymbolAddress((void**)&attn, g_attn);
    cudaGetSymbolAddress((void**)&Wr, g_Wr);

    cudaFuncSetAttribute(gemm_nt_mma,
                         cudaFuncAttributeMaxDynamicSharedMemorySize, DSMEM_SZ);

    const float scale = 1.0f / 32.0f;
    dim3 blk(256);

    round_kernel<<<((long)BATCH * SEQ * DIM / 4 + 255) / 256, blk>>>(
        x, xr, (long)BATCH * SEQ * DIM / 4);
    round_kernel<<<(DIM * DIM / 4 + 255) / 256, blk>>>(W, Wr, (long)DIM * DIM / 4);
    transpose_round<<<dim3(SEQ / 32, DIM / 32, BATCH), blk>>>(x, xT);

    gemm_nt_mma<<<dim3(SEQ / TN, SEQ / TM, BATCH), blk, DSMEM_SZ>>>(
        xr, xr, scores, DIM, DIM, DIM, SEQ,
        (long)SEQ * DIM, (long)SEQ * DIM, (long)SEQ * SEQ,
        scale, 1, 0, 0);

    softmax_kernel<<<BATCH * SEQ, blk>>>(scores);

    gemm_nt_mma<<<dim3(DIM / TN, SEQ / TM, BATCH), blk, DSMEM_SZ>>>(
        scores, xT, attn, SEQ, SEQ, SEQ, DIM,
        (long)SEQ * SEQ, (long)DIM * SEQ, (long)SEQ * DIM,
        1.0f, 0, 1, 1);

    gemm_nt_mma<<<dim3(DIM / TN, (BATCH * SEQ) / TM, 1), blk, DSMEM_SZ>>>(
        attn, Wr, out, DIM, DIM, DIM, DIM,
        0, 0, 0,
        1.0f, 0, 0, 0);
}